// round 11
// baseline (speedup 1.0000x reference)
#include <cuda_runtime.h>
#include <cuda_fp16.h>
#include <cstdint>

#define N_USERS 50000
#define D 128
#define N_EDGES 800000
#define E_PER_WARP 16
#define AS_STRIDE 132          // padded A smem stride in floats (conflict-free)

// -------- device scratch (no cudaMalloc allowed) --------
__device__ __half g_weighted_h[N_USERS * D];   // weighted = emb @ W in fp16

// ---------------------------------------------------------------------------
// Kernel 1: weighted_h = fp16(user_emb @ W) via tf32 mma.sync; out = user_emb.
// Block = 256 threads (8 warps), 128 rows per block.
// Staging phase does THREE things:
//   - A tile -> smem, tf32-pre-rounded, padded stride (+ residual copy with
//     the exact values)
//   - W -> smem directly in MMA B-fragment order, tf32-rounded (inline pack)
// Mainloop: per warp/kk: 4 conflict-free LDS + 16 conflict-free LDS.64 + 16 MMA.
// ---------------------------------------------------------------------------
__global__ __launch_bounds__(256) void gemm_kernel(
    const float* __restrict__ emb,
    const float* __restrict__ W,    // [D, D] fp32 row-major
    __half* __restrict__ wout,      // [N_USERS, D] fp16
    float* __restrict__ resout)     // [N_USERS, D] fp32 residual init
{
    extern __shared__ float smemf[];
    float*  As  = smemf;                                       // [128 * AS_STRIDE]
    float2* Wps = reinterpret_cast<float2*>(smemf + 128 * AS_STRIDE);  // [8192]

    const int tid = threadIdx.x;
    const int rowbase = blockIdx.x * 128;

    // ---- stage A tile (tf32-rounded) + fused residual copy out = emb ----
    {
        const float4* src = reinterpret_cast<const float4*>(emb);
        float4* dst = reinterpret_cast<float4*>(resout);
        float4* As4 = reinterpret_cast<float4*>(As);
        #pragma unroll
        for (int i = 0; i < 16; i++) {              // 128 rows * 32 float4 = 4096
            int idx = i * 256 + tid;
            int r = idx >> 5;
            int q = idx & 31;
            int gr = min(rowbase + r, N_USERS - 1);
            float4 v = src[(size_t)gr * 32 + q];
            if (rowbase + r < N_USERS)
                dst[(size_t)(rowbase + r) * 32 + q] = v;   // exact residual
            float4 t;
            asm("cvt.rna.tf32.f32 %0, %1;" : "=f"(t.x) : "f"(v.x));
            asm("cvt.rna.tf32.f32 %0, %1;" : "=f"(t.y) : "f"(v.y));
            asm("cvt.rna.tf32.f32 %0, %1;" : "=f"(t.z) : "f"(v.z));
            asm("cvt.rna.tf32.f32 %0, %1;" : "=f"(t.w) : "f"(v.w));
            As4[r * (AS_STRIDE / 4) + q] = t;       // stride 33 float4
        }
    }

    // ---- inline pack: W -> smem in B-fragment order, tf32-rounded ----
    // Wps[(kk*16 + j)*32 + lane] = { tf32(W[8kk+c][8j+gid]), tf32(W[8kk+c+4][8j+gid]) }
    // 32 consecutive tids read 4 rows x 32B of W => 4 full sectors, coalesced.
    #pragma unroll
    for (int i = 0; i < 32; i++) {                  // 8192 float2 entries
        int idx = i * 256 + tid;
        int lane = idx & 31;
        int j    = (idx >> 5) & 15;
        int kk   = idx >> 9;
        int cc   = lane & 3;
        int gg   = lane >> 2;
        int col  = j * 8 + gg;
        float w0 = W[(kk * 8 + cc) * D + col];
        float w1 = W[(kk * 8 + cc + 4) * D + col];
        float2 t;
        asm("cvt.rna.tf32.f32 %0, %1;" : "=f"(t.x) : "f"(w0));
        asm("cvt.rna.tf32.f32 %0, %1;" : "=f"(t.y) : "f"(w1));
        Wps[idx] = t;
    }
    __syncthreads();

    const int warp = tid >> 5;
    const int lane = tid & 31;
    const int gid  = lane >> 2;     // 0..7
    const int c    = lane & 3;      // 0..3

    const int trA = warp * 16 + gid;
    const int trB = warp * 16 + gid + 8;
    const int rA = rowbase + trA;
    const int rB = rowbase + trB;
    const float* pA = As + trA * AS_STRIDE;
    const float* pB = As + trB * AS_STRIDE;

    float acc[16][4];
    #pragma unroll
    for (int j = 0; j < 16; j++)
        #pragma unroll
        for (int q = 0; q < 4; q++) acc[j][q] = 0.f;

    #pragma unroll 1
    for (int kk = 0; kk < 16; kk++) {
        const int k0 = kk * 8;
        // A fragment already tf32-rounded in smem (conflict-free banks)
        unsigned a0 = __float_as_uint(pA[k0 + c]);
        unsigned a1 = __float_as_uint(pB[k0 + c]);
        unsigned a2 = __float_as_uint(pA[k0 + c + 4]);
        unsigned a3 = __float_as_uint(pB[k0 + c + 4]);

        const float2* wrow = Wps + kk * 16 * 32 + lane;
        #pragma unroll
        for (int j = 0; j < 16; j++) {
            float2 bp = wrow[j * 32];               // one LDS.64, conflict-free
            unsigned b0 = __float_as_uint(bp.x);
            unsigned b1 = __float_as_uint(bp.y);
            asm volatile(
                "mma.sync.aligned.m16n8k8.row.col.f32.tf32.tf32.f32 "
                "{%0,%1,%2,%3}, {%4,%5,%6,%7}, {%8,%9}, {%0,%1,%2,%3};"
                : "+f"(acc[j][0]), "+f"(acc[j][1]), "+f"(acc[j][2]), "+f"(acc[j][3])
                : "r"(a0), "r"(a1), "r"(a2), "r"(a3), "r"(b0), "r"(b1));
        }
    }

    // ---- epilogue: fp16 weighted ----
    #pragma unroll
    for (int j = 0; j < 16; j++) {
        const int col = j * 8 + 2 * c;
        __half2 hA = __floats2half2_rn(acc[j][0], acc[j][1]);
        __half2 hB = __floats2half2_rn(acc[j][2], acc[j][3]);
        if (rA < N_USERS) *reinterpret_cast<__half2*>(wout + (size_t)rA * D + col) = hA;
        if (rB < N_USERS) *reinterpret_cast<__half2*>(wout + (size_t)rB * D + col) = hB;
    }
}

// ---------------------------------------------------------------------------
// Kernel 2: out[rows[e]] += vals[e] * weighted_h[cols[e]]
// 16 edges per warp: lanes 0-15 hold metadata, 16 gathers in flight, 16 REDs.
// 800000 = 50000 warps * 16 exactly; no tail.
// ---------------------------------------------------------------------------
__global__ __launch_bounds__(256) void edge_kernel(
    const int* __restrict__ rows,
    const int* __restrict__ cols,
    const float* __restrict__ vals,
    const __half* __restrict__ weighted,
    float* __restrict__ out)
{
    const int warp = (blockIdx.x * blockDim.x + threadIdx.x) >> 5;
    const int lane = threadIdx.x & 31;
    const long long e0 = (long long)warp * E_PER_WARP;
    if (e0 >= N_EDGES) return;

    const int eidx = (int)e0 + (lane & (E_PER_WARP - 1));
    int   ri = __ldg(rows + eidx);
    int   ci = __ldg(cols + eidx);
    float vi = __ldg(vals + eidx);

    uint2 pk[E_PER_WARP];
    #pragma unroll
    for (int i = 0; i < E_PER_WARP; i++) {
        int cc = __shfl_sync(0xffffffffu, ci, i);
        pk[i] = *reinterpret_cast<const uint2*>(weighted + (size_t)cc * D + lane * 4);
    }

    #pragma unroll
    for (int i = 0; i < E_PER_WARP; i++) {
        int   r = __shfl_sync(0xffffffffu, ri, i);
        float v = __shfl_sync(0xffffffffu, vi, i);
        __half2 h0 = *reinterpret_cast<__half2*>(&pk[i].x);
        __half2 h1 = *reinterpret_cast<__half2*>(&pk[i].y);
        float2 f0 = __half22float2(h0);
        float2 f1 = __half22float2(h1);
        float px = v * f0.x, py = v * f0.y, pz = v * f1.x, pw = v * f1.y;
        float* dst = out + (size_t)r * D + lane * 4;
        asm volatile("red.global.add.v4.f32 [%0], {%1,%2,%3,%4};"
                     :: "l"(dst), "f"(px), "f"(py), "f"(pz), "f"(pw)
                     : "memory");
    }
}

// ---------------------------------------------------------------------------
// Launch
// ---------------------------------------------------------------------------
extern "C" void kernel_launch(void* const* d_in, const int* in_sizes, int n_in,
                              void* d_out, int out_size)
{
    const float* user_emb = (const float*)d_in[0];
    const float* social_w = (const float*)d_in[1];
    const int*   rows     = (const int*)d_in[2];
    const int*   cols     = (const int*)d_in[3];
    const float* vals     = (const float*)d_in[4];
    float*       out      = (float*)d_out;

    __half* weighted;  cudaGetSymbolAddress((void**)&weighted, g_weighted_h);

    // 1. GEMM (tf32 tensor cores) + inline W pack + fused residual init
    {
        const int smem_bytes = 128 * AS_STRIDE * sizeof(float)
                             + 16 * 16 * 32 * sizeof(float2);   // 67584 + 65536
        cudaFuncSetAttribute(gemm_kernel,
                             cudaFuncAttributeMaxDynamicSharedMemorySize, smem_bytes);
        int nblk = (N_USERS + 127) / 128;                       // 391
        gemm_kernel<<<nblk, 256, smem_bytes>>>(user_emb, social_w, weighted, out);
    }

    // 2. scatter-add edges, 16 edges per warp
    {
        int nwarps = N_EDGES / E_PER_WARP;              // 50000
        int nblk = (nwarps * 32 + 255) / 256;           // 6250
        edge_kernel<<<nblk, 256>>>(rows, cols, vals, weighted, out);
    }
}

// round 12
// speedup vs baseline: 1.0695x; 1.0695x over previous
#include <cuda_runtime.h>
#include <cuda_fp16.h>
#include <cstdint>

#define N_USERS 50000
#define D 128
#define N_EDGES 800000
#define E_PER_WARP 8
#define AS_STRIDE 132          // padded A smem stride in floats (conflict-free)

// -------- device scratch (no cudaMalloc allowed) --------
__device__ __half g_weighted_h[N_USERS * D];   // weighted = emb @ W in fp16
__device__ float2 g_wpack[16 * 16 * 32];       // W pre-packed into MMA B fragments

// ---------------------------------------------------------------------------
// Kernel 0: pack W into B-fragment order, tf32-rounded.
// Wp[(kk*16 + j)*32 + lane] = { W[8kk + c][8j + gid], W[8kk + c + 4][8j + gid] }
// with c = lane&3, gid = lane>>2.  (m16n8k8.row.col B fragment layout.)
// ---------------------------------------------------------------------------
__global__ void pack_w_kernel(const float* __restrict__ W, float2* __restrict__ Wp)
{
    int idx = blockIdx.x * blockDim.x + threadIdx.x;
    if (idx >= 16 * 16 * 32) return;
    int lane = idx & 31;
    int j    = (idx >> 5) & 15;
    int kk   = idx >> 9;
    int c    = lane & 3;
    int gid  = lane >> 2;
    int col  = j * 8 + gid;
    float w0 = W[(kk * 8 + c) * D + col];
    float w1 = W[(kk * 8 + c + 4) * D + col];
    unsigned t0, t1;
    asm("cvt.rna.tf32.f32 %0, %1;" : "=r"(t0) : "f"(w0));
    asm("cvt.rna.tf32.f32 %0, %1;" : "=r"(t1) : "f"(w1));
    Wp[idx] = make_float2(__uint_as_float(t0), __uint_as_float(t1));
}

// ---------------------------------------------------------------------------
// Kernel 1: weighted_h = fp16(user_emb @ W) via tf32 mma.sync; out = user_emb.
// Block = 256 threads (8 warps), 128 rows per block.
// A tile staged in smem (padded stride), B fragments from packed smem copy.
// ---------------------------------------------------------------------------
__global__ __launch_bounds__(256) void gemm_kernel(
    const float* __restrict__ emb,
    const float2* __restrict__ Wp,  // packed B fragments (tf32 bits)
    __half* __restrict__ wout,      // [N_USERS, D] fp16
    float* __restrict__ resout)     // [N_USERS, D] fp32 residual init
{
    extern __shared__ float smemf[];
    float*  As  = smemf;                            // [128 * AS_STRIDE] floats
    float2* Wps = reinterpret_cast<float2*>(smemf + 128 * AS_STRIDE);  // [8192]

    const int tid = threadIdx.x;
    const int rowbase = blockIdx.x * 128;

    // ---- stage A tile (coalesced float4) + fused residual copy out = emb ----
    {
        const float4* src = reinterpret_cast<const float4*>(emb);
        float4* dst = reinterpret_cast<float4*>(resout);
        float4* As4 = reinterpret_cast<float4*>(As);
        #pragma unroll
        for (int i = 0; i < 16; i++) {              // 128 rows * 32 float4
            int idx = i * 256 + tid;
            int r = idx >> 5;                       // tile row
            int q = idx & 31;                       // float4 within row
            int gr = min(rowbase + r, N_USERS - 1);
            float4 v = src[(size_t)gr * 32 + q];
            As4[r * (AS_STRIDE / 4) + q] = v;       // stride 33 float4
            if (rowbase + r < N_USERS)
                dst[(size_t)(rowbase + r) * 32 + q] = v;
        }
    }

    // ---- stage packed W fragments (coalesced float4 over float2 pairs) ----
    {
        const float4* srcp = reinterpret_cast<const float4*>(Wp);
        float4* dstp = reinterpret_cast<float4*>(Wps);
        #pragma unroll
        for (int i = 0; i < 16; i++)                // 4096 float4
            dstp[i * 256 + tid] = srcp[i * 256 + tid];
    }
    __syncthreads();

    const int warp = tid >> 5;
    const int lane = tid & 31;
    const int gid  = lane >> 2;     // 0..7
    const int c    = lane & 3;      // 0..3

    const int trA = warp * 16 + gid;        // tile rows
    const int trB = warp * 16 + gid + 8;
    const int rA = rowbase + trA;
    const int rB = rowbase + trB;
    const float* pA = As + trA * AS_STRIDE;
    const float* pB = As + trB * AS_STRIDE;

    float acc[16][4];
    #pragma unroll
    for (int j = 0; j < 16; j++)
        #pragma unroll
        for (int q = 0; q < 4; q++) acc[j][q] = 0.f;

    #pragma unroll 1
    for (int kk = 0; kk < 16; kk++) {
        const int k0 = kk * 8;
        // A fragment (conflict-free: bank = (4*gid + c + 8kk) % 32, all distinct)
        float a0f = pA[k0 + c];
        float a1f = pB[k0 + c];
        float a2f = pA[k0 + c + 4];
        float a3f = pB[k0 + c + 4];
        unsigned a0, a1, a2, a3;
        asm("cvt.rna.tf32.f32 %0, %1;" : "=r"(a0) : "f"(a0f));
        asm("cvt.rna.tf32.f32 %0, %1;" : "=r"(a1) : "f"(a1f));
        asm("cvt.rna.tf32.f32 %0, %1;" : "=r"(a2) : "f"(a2f));
        asm("cvt.rna.tf32.f32 %0, %1;" : "=r"(a3) : "f"(a3f));

        const float2* wrow = Wps + kk * 16 * 32 + lane;
        #pragma unroll
        for (int j = 0; j < 16; j++) {
            float2 bp = wrow[j * 32];               // one LDS.64, conflict-free
            unsigned b0 = __float_as_uint(bp.x);
            unsigned b1 = __float_as_uint(bp.y);
            asm volatile(
                "mma.sync.aligned.m16n8k8.row.col.f32.tf32.tf32.f32 "
                "{%0,%1,%2,%3}, {%4,%5,%6,%7}, {%8,%9}, {%0,%1,%2,%3};"
                : "+f"(acc[j][0]), "+f"(acc[j][1]), "+f"(acc[j][2]), "+f"(acc[j][3])
                : "r"(a0), "r"(a1), "r"(a2), "r"(a3), "r"(b0), "r"(b1));
        }
    }

    // ---- epilogue: fp16 weighted ----
    #pragma unroll
    for (int j = 0; j < 16; j++) {
        const int col = j * 8 + 2 * c;
        __half2 hA = __floats2half2_rn(acc[j][0], acc[j][1]);
        __half2 hB = __floats2half2_rn(acc[j][2], acc[j][3]);
        if (rA < N_USERS) *reinterpret_cast<__half2*>(wout + (size_t)rA * D + col) = hA;
        if (rB < N_USERS) *reinterpret_cast<__half2*>(wout + (size_t)rB * D + col) = hB;
    }
}

// ---------------------------------------------------------------------------
// Kernel 2: out[rows[e]] += vals[e] * weighted_h[cols[e]]
// 8 edges per warp: lanes 0-7 hold metadata, 8 gathers in flight, 8 REDs.
// 800000 = 100000 warps * 8 exactly; no tail.
// ---------------------------------------------------------------------------
__global__ __launch_bounds__(256) void edge_kernel(
    const int* __restrict__ rows,
    const int* __restrict__ cols,
    const float* __restrict__ vals,
    const __half* __restrict__ weighted,
    float* __restrict__ out)
{
    const int warp = (blockIdx.x * blockDim.x + threadIdx.x) >> 5;
    const int lane = threadIdx.x & 31;
    const long long e0 = (long long)warp * E_PER_WARP;
    if (e0 >= N_EDGES) return;

    const int eidx = (int)e0 + (lane & (E_PER_WARP - 1));
    int   ri = __ldg(rows + eidx);
    int   ci = __ldg(cols + eidx);
    float vi = __ldg(vals + eidx);

    uint2 pk[E_PER_WARP];
    #pragma unroll
    for (int i = 0; i < E_PER_WARP; i++) {
        int cc = __shfl_sync(0xffffffffu, ci, i);
        pk[i] = *reinterpret_cast<const uint2*>(weighted + (size_t)cc * D + lane * 4);
    }

    #pragma unroll
    for (int i = 0; i < E_PER_WARP; i++) {
        int   r = __shfl_sync(0xffffffffu, ri, i);
        float v = __shfl_sync(0xffffffffu, vi, i);
        __half2 h0 = *reinterpret_cast<__half2*>(&pk[i].x);
        __half2 h1 = *reinterpret_cast<__half2*>(&pk[i].y);
        float2 f0 = __half22float2(h0);
        float2 f1 = __half22float2(h1);
        float px = v * f0.x, py = v * f0.y, pz = v * f1.x, pw = v * f1.y;
        float* dst = out + (size_t)r * D + lane * 4;
        asm volatile("red.global.add.v4.f32 [%0], {%1,%2,%3,%4};"
                     :: "l"(dst), "f"(px), "f"(py), "f"(pz), "f"(pw)
                     : "memory");
    }
}

// ---------------------------------------------------------------------------
// Launch
// ---------------------------------------------------------------------------
extern "C" void kernel_launch(void* const* d_in, const int* in_sizes, int n_in,
                              void* d_out, int out_size)
{
    const float* user_emb = (const float*)d_in[0];
    const float* social_w = (const float*)d_in[1];
    const int*   rows     = (const int*)d_in[2];
    const int*   cols     = (const int*)d_in[3];
    const float* vals     = (const float*)d_in[4];
    float*       out      = (float*)d_out;

    __half* weighted;  cudaGetSymbolAddress((void**)&weighted, g_weighted_h);
    float2* wpack;     cudaGetSymbolAddress((void**)&wpack,    g_wpack);

    // 0. pack W into B-fragment order (tiny)
    pack_w_kernel<<<32, 256>>>(social_w, wpack);

    // 1. GEMM (tf32 tensor cores) + fused residual init
    {
        const int smem_bytes = 128 * AS_STRIDE * sizeof(float)
                             + 16 * 16 * 32 * sizeof(float2);   // 67584 + 65536
        cudaFuncSetAttribute(gemm_kernel,
                             cudaFuncAttributeMaxDynamicSharedMemorySize, smem_bytes);
        int nblk = (N_USERS + 127) / 128;                       // 391
        gemm_kernel<<<nblk, 256, smem_bytes>>>(user_emb, wpack, weighted, out);
    }

    // 2. scatter-add edges, 8 edges per warp
    {
        int nwarps = N_EDGES / E_PER_WARP;              // 100000
        int nblk = (nwarps * 32 + 255) / 256;           // 12500
        edge_kernel<<<nblk, 256>>>(rows, cols, vals, weighted, out);
    }
}